// round 5
// baseline (speedup 1.0000x reference)
#include <cuda_runtime.h>
#include <cstdint>
#include <cstddef>

#define D    4096
#define NH   32
#define H    128
#define S    4096
#define KMASK (-2.3819763e+38f)

// ---------------- scratch (device globals; no allocation allowed) ----------
__device__ __align__(16) float g_qkvp[64 * 96 * 128];   // qkv gemv partials
__device__ __align__(16) float g_q[NH * H];             // rope'd + scaled q
__device__ __align__(16) float g_knew[NH * H];          // rope'd new k row
__device__ __align__(16) float g_vnew[NH * H];          // new v row
__device__ float g_pm[NH * 64];                         // per-chunk max
__device__ float g_pl[NH * 64];                         // per-chunk sum
__device__ __align__(16) float g_pacc[64 * NH * H];     // per-chunk p·v partials
__device__ __align__(16) float g_enc[NH * H];           // final encoded
__device__ __align__(16) float g_opart[64 * D];         // [nh-chunk][d]

// ---------------- K1: qkv = x @ w_qkv, partial over D ----------------------
// grid (96, 16): blockIdx.x = s*32+n, blockIdx.y = D-chunk of 256
__global__ void __launch_bounds__(128) k_qkv_partial(const float* __restrict__ x,
                                                     const float* __restrict__ w) {
    int sn = blockIdx.x;
    int dchunk = blockIdx.y;
    int tid = threadIdx.x;
    int hv = tid & 31;
    int ds = tid >> 5;

    __shared__ float xs[256];
    int dbase = dchunk * 256;
    for (int i = tid; i < 256; i += 128) xs[i] = x[dbase + i];
    __syncthreads();

    const float4* wv = (const float4*)(w + (size_t)sn * D * H + (size_t)dbase * H);
    float4 acc = make_float4(0.f, 0.f, 0.f, 0.f);
    int d0 = ds * 64;
#pragma unroll 8
    for (int d = d0; d < d0 + 64; ++d) {
        float xv = xs[d];
        float4 wq = wv[d * 32 + hv];
        acc.x += xv * wq.x; acc.y += xv * wq.y;
        acc.z += xv * wq.z; acc.w += xv * wq.w;
    }
    int p = dchunk * 4 + ds;                      // 0..63
    ((float4*)g_qkvp)[((size_t)p * 96 + sn) * 32 + hv] = acc;
}

// ---------------- K2: reduce partials, RoPE, scatter new rows --------------
__global__ void __launch_bounds__(128) k_qkv_rope(const int* __restrict__ segp,
                                                  const int* __restrict__ tsp,
                                                  float* __restrict__ k_out,
                                                  float* __restrict__ v_out) {
    int sn = blockIdx.x;
    int h = threadIdx.x;
    int s = sn >> 5, n = sn & 31;

    float val = 0.f;
#pragma unroll
    for (int p = 0; p < 64; ++p) val += g_qkvp[((size_t)p * 96 + sn) * 128 + h];

    __shared__ float sm[128];
    sm[h] = val;
    __syncthreads();

    int ts = tsp[0];
    if (s == 2) {
        g_vnew[n * 128 + h] = val;
        v_out[((size_t)ts * NH + n) * H + h] = val;
        return;
    }
    float pos = (float)segp[0];
    int i = h & 63;
    float timescale = powf(10000.f, (float)i * (1.f / 64.f));
    float ang = pos / timescale;
    float sn_, cs;
    sincosf(ang, &sn_, &cs);
    float out;
    if (h < 64) out = sm[h] * cs - sm[h + 64] * sn_;
    else        out = sm[h] * cs + sm[h - 64] * sn_;
    if (s == 0) {
        g_q[n * 128 + h] = out * 0.08838834764831845f;  // head_dim^-0.5
    } else {
        g_knew[n * 128 + h] = out;
        k_out[((size_t)ts * NH + n) * H + h] = out;
    }
}

// ---------------- K3: flash attention + k/v cache copy ---------------------
// grid (64 s-chunks of 64, NH), block 256 = 8 warps; warp does 8 s-rows.
// Streams k AND v once; emits per-chunk (m, l, acc[128]) partials.
__global__ void __launch_bounds__(256) k_flash(const float* __restrict__ k_in,
                                               const float* __restrict__ v_in,
                                               const float* __restrict__ mask,
                                               const int* __restrict__ tsp,
                                               float* __restrict__ k_out,
                                               float* __restrict__ v_out) {
    int warp = threadIdx.x >> 5;
    int lane = threadIdx.x & 31;
    int n = blockIdx.y;
    int c = blockIdx.x;
    int s0 = c * 64 + warp * 8;
    int ts = tsp[0];

    float4 qq = ((const float4*)g_q)[n * 32 + lane];

    // ---- K rows: front-batched load (MLP 8), copy, dot ----
    float4 kk[8];
#pragma unroll
    for (int i = 0; i < 8; ++i) {
        int s = s0 + i;
        size_t ridx = (((size_t)s * NH + n) * H) >> 2;
        kk[i] = (s == ts) ? ((const float4*)g_knew)[n * 32 + lane]
                          : ((const float4*)k_in)[ridx + lane];
    }
#pragma unroll
    for (int i = 0; i < 8; ++i) {
        int s = s0 + i;
        if (s != ts) {
            size_t ridx = (((size_t)s * NH + n) * H) >> 2;
            ((float4*)k_out)[ridx + lane] = kk[i];
        }
    }

    float lg[8];
#pragma unroll
    for (int i = 0; i < 8; ++i) {
        int s = s0 + i;
        float dot = kk[i].x * qq.x + kk[i].y * qq.y + kk[i].z * qq.z + kk[i].w * qq.w;
#pragma unroll
        for (int off = 16; off; off >>= 1)
            dot += __shfl_xor_sync(0xffffffffu, dot, off);
        lg[i] = (mask[s] >= 0.5f * KMASK) ? dot : KMASK;
    }

    // warp-local softmax over 8 rows
    float m = lg[0];
#pragma unroll
    for (int i = 1; i < 8; ++i) m = fmaxf(m, lg[i]);
    float p[8], l = 0.f;
#pragma unroll
    for (int i = 0; i < 8; ++i) { p[i] = __expf(lg[i] - m); l += p[i]; }

    // ---- V rows: front-batched load, copy, weighted accumulate ----
    float4 vv[8];
#pragma unroll
    for (int i = 0; i < 8; ++i) {
        int s = s0 + i;
        size_t ridx = (((size_t)s * NH + n) * H) >> 2;
        vv[i] = (s == ts) ? ((const float4*)g_vnew)[n * 32 + lane]
                          : ((const float4*)v_in)[ridx + lane];
    }
#pragma unroll
    for (int i = 0; i < 8; ++i) {
        int s = s0 + i;
        if (s != ts) {
            size_t ridx = (((size_t)s * NH + n) * H) >> 2;
            ((float4*)v_out)[ridx + lane] = vv[i];
        }
    }

    float4 acc = make_float4(0.f, 0.f, 0.f, 0.f);
#pragma unroll
    for (int i = 0; i < 8; ++i) {
        acc.x += p[i] * vv[i].x; acc.y += p[i] * vv[i].y;
        acc.z += p[i] * vv[i].z; acc.w += p[i] * vv[i].w;
    }

    // ---- block merge across 8 warps ----
    __shared__ float4 red[8][32];
    __shared__ float sm_m[8], sm_l[8];
    red[warp][lane] = acc;
    if (lane == 0) { sm_m[warp] = m; sm_l[warp] = l; }
    __syncthreads();
    if (warp == 0) {
        float bm = sm_m[0];
#pragma unroll
        for (int w = 1; w < 8; ++w) bm = fmaxf(bm, sm_m[w]);
        float bl = 0.f;
        float4 t = make_float4(0.f, 0.f, 0.f, 0.f);
#pragma unroll
        for (int w = 0; w < 8; ++w) {
            float e = __expf(sm_m[w] - bm);
            bl += sm_l[w] * e;
            float4 o = red[w][lane];
            t.x += e * o.x; t.y += e * o.y; t.z += e * o.z; t.w += e * o.w;
        }
        ((float4*)g_pacc)[((size_t)c * NH + n) * 32 + lane] = t;
        if (lane == 0) {
            g_pm[n * 64 + c] = bm;
            g_pl[n * 64 + c] = bl;
        }
    }
}

// ---------------- K4: combine chunk partials per head ----------------------
// grid NH, block 128 (h); all threads redundantly merge 64 (m,l) from L2
__global__ void __launch_bounds__(128) k_combine() {
    int n = blockIdx.x;
    int h = threadIdx.x;

    float mg = -3.4e38f;
#pragma unroll 8
    for (int c = 0; c < 64; ++c) mg = fmaxf(mg, g_pm[n * 64 + c]);
    float lsum = 0.f, acc = 0.f;
#pragma unroll 8
    for (int c = 0; c < 64; ++c) {
        float e = __expf(g_pm[n * 64 + c] - mg);
        lsum += g_pl[n * 64 + c] * e;
        acc += g_pacc[((size_t)c * NH + n) * 128 + h] * e;
    }
    g_enc[n * 128 + h] = acc / lsum;
}

// ---------------- K5: output GEMV partials ---------------------------------
// grid (8 d-tiles of 512, 64 nh-chunks of 64), block 128: thread owns 4 d
__global__ void __launch_bounds__(128) k_out_gemv(const float* __restrict__ w_out) {
    __shared__ float enc_s[64];
    int tid = threadIdx.x;
    int nh0 = blockIdx.y * 64;
    if (tid < 64) enc_s[tid] = g_enc[nh0 + tid];
    __syncthreads();

    int d4 = blockIdx.x * 128 + tid;             // float4 index over d
    const float4* wv = (const float4*)w_out;
    float4 acc = make_float4(0.f, 0.f, 0.f, 0.f);
#pragma unroll 8
    for (int j = 0; j < 64; ++j) {
        float e = enc_s[j];
        float4 w4 = wv[(size_t)(nh0 + j) * (D / 4) + d4];
        acc.x += e * w4.x; acc.y += e * w4.y;
        acc.z += e * w4.z; acc.w += e * w4.w;
    }
    ((float4*)g_opart)[(size_t)blockIdx.y * (D / 4) + d4] = acc;
}

// ---------------- K6: final output reduce ----------------------------------
__global__ void __launch_bounds__(128) k_out_reduce(float* __restrict__ attn) {
    int d = blockIdx.x * 128 + threadIdx.x;
    float v = 0.f;
#pragma unroll
    for (int c = 0; c < 64; ++c) v += g_opart[(size_t)c * D + d];
    attn[d] = v;
}

// ---------------- launch ----------------------------------------------------
extern "C" void kernel_launch(void* const* d_in, const int* in_sizes, int n_in,
                              void* d_out, int out_size) {
    const float* x      = (const float*)d_in[0];
    const float* w_qkv  = (const float*)d_in[1];
    const float* w_out  = (const float*)d_in[2];
    const float* k_in   = (const float*)d_in[3];
    const float* v_in   = (const float*)d_in[4];
    const float* mask   = (const float*)d_in[5];
    const int*   segp   = (const int*)d_in[6];
    const int*   tsp    = (const int*)d_in[7];

    float* out   = (float*)d_out;
    float* k_out = out;
    float* v_out = out + (size_t)S * NH * H;
    float* attn  = out + 2ull * S * NH * H;

    k_qkv_partial<<<dim3(96, 16), 128>>>(x, w_qkv);
    k_qkv_rope<<<96, 128>>>(segp, tsp, k_out, v_out);
    k_flash<<<dim3(64, NH), 256>>>(k_in, v_in, mask, tsp, k_out, v_out);
    k_combine<<<NH, 128>>>();
    k_out_gemv<<<dim3(8, 64), 128>>>(w_out);
    k_out_reduce<<<32, 128>>>(attn);
}

// round 7
// speedup vs baseline: 1.0859x; 1.0859x over previous
#include <cuda_runtime.h>
#include <cstdint>
#include <cstddef>

#define D    4096
#define NH   32
#define H    128
#define S    4096
#define KMASK (-2.3819763e+38f)

// ---------------- scratch (device globals; no allocation allowed) ----------
__device__ __align__(16) float g_qkvp[64 * 96 * 128];   // qkv gemv partials
__device__ __align__(16) float g_q[NH * H];             // rope'd + scaled q
__device__ __align__(16) float g_knew[NH * H];          // rope'd new k row
__device__ __align__(16) float g_vnew[NH * H];          // new v row
__device__ float g_pm[NH * 64];                         // per-chunk max
__device__ float g_pl[NH * 64];                         // per-chunk sum
__device__ __align__(16) float g_pacc[NH * 64 * H];     // [n][c][h] p·v partials
__device__ __align__(16) float g_enc[NH * H];           // final encoded
__device__ __align__(16) float g_opart[64 * D];         // [nh-chunk][d]

// ---------------- K1: qkv = x @ w_qkv, partial over D ----------------------
// grid (96, 16): blockIdx.x = s*32+n, blockIdx.y = D-chunk of 256
__global__ void __launch_bounds__(128) k_qkv_partial(const float* __restrict__ x,
                                                     const float* __restrict__ w) {
    int sn = blockIdx.x;
    int dchunk = blockIdx.y;
    int tid = threadIdx.x;
    int hv = tid & 31;
    int ds = tid >> 5;

    __shared__ float xs[256];
    int dbase = dchunk * 256;
    for (int i = tid; i < 256; i += 128) xs[i] = x[dbase + i];
    __syncthreads();

    const float4* wv = (const float4*)(w + (size_t)sn * D * H + (size_t)dbase * H);
    float4 acc = make_float4(0.f, 0.f, 0.f, 0.f);
    int d0 = ds * 64;
#pragma unroll 8
    for (int d = d0; d < d0 + 64; ++d) {
        float xv = xs[d];
        float4 wq = wv[d * 32 + hv];
        acc.x += xv * wq.x; acc.y += xv * wq.y;
        acc.z += xv * wq.z; acc.w += xv * wq.w;
    }
    int p = dchunk * 4 + ds;                      // 0..63
    ((float4*)g_qkvp)[((size_t)p * 96 + sn) * 32 + hv] = acc;
}

// ---------------- K2: reduce partials, RoPE, scatter new rows --------------
__global__ void __launch_bounds__(128) k_qkv_rope(const int* __restrict__ segp,
                                                  const int* __restrict__ tsp,
                                                  float* __restrict__ k_out,
                                                  float* __restrict__ v_out) {
    int sn = blockIdx.x;
    int h = threadIdx.x;
    int s = sn >> 5, n = sn & 31;

    float val = 0.f;
#pragma unroll
    for (int p = 0; p < 64; ++p) val += g_qkvp[((size_t)p * 96 + sn) * 128 + h];

    __shared__ float sm[128];
    sm[h] = val;
    __syncthreads();

    int ts = tsp[0];
    if (s == 2) {
        g_vnew[n * 128 + h] = val;
        v_out[((size_t)ts * NH + n) * H + h] = val;
        return;
    }
    float pos = (float)segp[0];
    int i = h & 63;
    float timescale = powf(10000.f, (float)i * (1.f / 64.f));
    float ang = pos / timescale;
    float sn_, cs;
    sincosf(ang, &sn_, &cs);
    float out;
    if (h < 64) out = sm[h] * cs - sm[h + 64] * sn_;
    else        out = sm[h] * cs + sm[h - 64] * sn_;
    if (s == 0) {
        g_q[n * 128 + h] = out * 0.08838834764831845f;  // head_dim^-0.5
    } else {
        g_knew[n * 128 + h] = out;
        k_out[((size_t)ts * NH + n) * H + h] = out;
    }
}

// ---------------- K3: flash attention + k/v cache copy ---------------------
// grid (64 s-chunks of 64, NH), block 256 = 8 warps; warp does 8 s-rows.
__global__ void __launch_bounds__(256) k_flash(const float* __restrict__ k_in,
                                               const float* __restrict__ v_in,
                                               const float* __restrict__ mask,
                                               const int* __restrict__ tsp,
                                               float* __restrict__ k_out,
                                               float* __restrict__ v_out) {
    int warp = threadIdx.x >> 5;
    int lane = threadIdx.x & 31;
    int n = blockIdx.y;
    int c = blockIdx.x;
    int s0 = c * 64 + warp * 8;
    int ts = tsp[0];

    float4 qq = ((const float4*)g_q)[n * 32 + lane];

    // ---- K rows: front-batched load (MLP 8), copy, dot ----
    float4 kk[8];
#pragma unroll
    for (int i = 0; i < 8; ++i) {
        int s = s0 + i;
        size_t ridx = (((size_t)s * NH + n) * H) >> 2;
        kk[i] = (s == ts) ? ((const float4*)g_knew)[n * 32 + lane]
                          : ((const float4*)k_in)[ridx + lane];
    }
#pragma unroll
    for (int i = 0; i < 8; ++i) {
        int s = s0 + i;
        if (s != ts) {
            size_t ridx = (((size_t)s * NH + n) * H) >> 2;
            ((float4*)k_out)[ridx + lane] = kk[i];
        }
    }

    float lg[8];
#pragma unroll
    for (int i = 0; i < 8; ++i) {
        int s = s0 + i;
        float dot = kk[i].x * qq.x + kk[i].y * qq.y + kk[i].z * qq.z + kk[i].w * qq.w;
#pragma unroll
        for (int off = 16; off; off >>= 1)
            dot += __shfl_xor_sync(0xffffffffu, dot, off);
        lg[i] = (mask[s] >= 0.5f * KMASK) ? dot : KMASK;
    }

    // warp-local softmax over 8 rows
    float m = lg[0];
#pragma unroll
    for (int i = 1; i < 8; ++i) m = fmaxf(m, lg[i]);
    float p[8], l = 0.f;
#pragma unroll
    for (int i = 0; i < 8; ++i) { p[i] = __expf(lg[i] - m); l += p[i]; }

    // ---- V rows: front-batched load, copy, weighted accumulate ----
    float4 vv[8];
#pragma unroll
    for (int i = 0; i < 8; ++i) {
        int s = s0 + i;
        size_t ridx = (((size_t)s * NH + n) * H) >> 2;
        vv[i] = (s == ts) ? ((const float4*)g_vnew)[n * 32 + lane]
                          : ((const float4*)v_in)[ridx + lane];
    }
#pragma unroll
    for (int i = 0; i < 8; ++i) {
        int s = s0 + i;
        if (s != ts) {
            size_t ridx = (((size_t)s * NH + n) * H) >> 2;
            ((float4*)v_out)[ridx + lane] = vv[i];
        }
    }

    float4 acc = make_float4(0.f, 0.f, 0.f, 0.f);
#pragma unroll
    for (int i = 0; i < 8; ++i) {
        acc.x += p[i] * vv[i].x; acc.y += p[i] * vv[i].y;
        acc.z += p[i] * vv[i].z; acc.w += p[i] * vv[i].w;
    }

    // ---- block merge across 8 warps ----
    __shared__ float4 red[8][32];
    __shared__ float sm_m[8], sm_l[8];
    red[warp][lane] = acc;
    if (lane == 0) { sm_m[warp] = m; sm_l[warp] = l; }
    __syncthreads();
    if (warp == 0) {
        float bm = sm_m[0];
#pragma unroll
        for (int w = 1; w < 8; ++w) bm = fmaxf(bm, sm_m[w]);
        float bl = 0.f;
        float4 t = make_float4(0.f, 0.f, 0.f, 0.f);
#pragma unroll
        for (int w = 0; w < 8; ++w) {
            float e = __expf(sm_m[w] - bm);
            bl += sm_l[w] * e;
            float4 o = red[w][lane];
            t.x += e * o.x; t.y += e * o.y; t.z += e * o.z; t.w += e * o.w;
        }
        ((float4*)g_pacc)[((size_t)n * 64 + c) * 32 + lane] = t;   // [n][c][h]
        if (lane == 0) {
            g_pm[n * 64 + c] = bm;
            g_pl[n * 64 + c] = bl;
        }
    }
}

// ---------------- K4: combine chunk partials per head (parallel) -----------
// grid NH, block 512: warp 0 computes stats; 4 groups of 128 sum 16 chunks each
__global__ void __launch_bounds__(512) k_combine() {
    int n = blockIdx.x;
    int tid = threadIdx.x;
    int h = tid & 127;
    int cg = tid >> 7;                            // 0..3

    __shared__ float s_e[64];
    __shared__ float s_linv;
    __shared__ float s_acc[4][128];

    if (tid < 32) {
        float m0 = g_pm[n * 64 + tid];
        float m1 = g_pm[n * 64 + tid + 32];
        float m = fmaxf(m0, m1);
#pragma unroll
        for (int off = 16; off; off >>= 1)
            m = fmaxf(m, __shfl_xor_sync(0xffffffffu, m, off));
        float e0 = __expf(m0 - m);
        float e1 = __expf(m1 - m);
        s_e[tid] = e0;
        s_e[tid + 32] = e1;
        float l = g_pl[n * 64 + tid] * e0 + g_pl[n * 64 + tid + 32] * e1;
#pragma unroll
        for (int off = 16; off; off >>= 1)
            l += __shfl_xor_sync(0xffffffffu, l, off);
        if (tid == 0) s_linv = 1.f / l;
    }
    __syncthreads();

    const float* base = g_pacc + (size_t)n * 64 * 128;
    float acc = 0.f;
    int c0 = cg * 16;
#pragma unroll 16
    for (int c = c0; c < c0 + 16; ++c)
        acc += base[c * 128 + h] * s_e[c];
    s_acc[cg][h] = acc;
    __syncthreads();
    if (tid < 128) {
        float v = (s_acc[0][h] + s_acc[1][h]) + (s_acc[2][h] + s_acc[3][h]);
        g_enc[n * 128 + h] = v * s_linv;
    }
}

// ---------------- K5: output GEMV partials ---------------------------------
// grid (8 d-tiles of 512, 64 nh-chunks of 64), block 128: thread owns 4 d
__global__ void __launch_bounds__(128) k_out_gemv(const float* __restrict__ w_out) {
    __shared__ float enc_s[64];
    int tid = threadIdx.x;
    int nh0 = blockIdx.y * 64;
    if (tid < 64) enc_s[tid] = g_enc[nh0 + tid];
    __syncthreads();

    int d4 = blockIdx.x * 128 + tid;             // float4 index over d
    const float4* wv = (const float4*)w_out;
    float4 acc = make_float4(0.f, 0.f, 0.f, 0.f);
#pragma unroll 8
    for (int j = 0; j < 64; ++j) {
        float e = enc_s[j];
        float4 w4 = wv[(size_t)(nh0 + j) * (D / 4) + d4];
        acc.x += e * w4.x; acc.y += e * w4.y;
        acc.z += e * w4.z; acc.w += e * w4.w;
    }
    ((float4*)g_opart)[(size_t)blockIdx.y * (D / 4) + d4] = acc;
}

// ---------------- K6: final output reduce (float4) -------------------------
// grid 8, block 128: thread owns one float4 over d
__global__ void __launch_bounds__(128) k_out_reduce(float* __restrict__ attn) {
    int d4 = blockIdx.x * 128 + threadIdx.x;     // float4 index over d
    float4 v = make_float4(0.f, 0.f, 0.f, 0.f);
#pragma unroll
    for (int c = 0; c < 64; ++c) {
        float4 o = ((const float4*)g_opart)[(size_t)c * (D / 4) + d4];
        v.x += o.x; v.y += o.y; v.z += o.z; v.w += o.w;
    }
    ((float4*)attn)[d4] = v;
}

// ---------------- launch ----------------------------------------------------
extern "C" void kernel_launch(void* const* d_in, const int* in_sizes, int n_in,
                              void* d_out, int out_size) {
    const float* x      = (const float*)d_in[0];
    const float* w_qkv  = (const float*)d_in[1];
    const float* w_out  = (const float*)d_in[2];
    const float* k_in   = (const float*)d_in[3];
    const float* v_in   = (const float*)d_in[4];
    const float* mask   = (const float*)d_in[5];
    const int*   segp   = (const int*)d_in[6];
    const int*   tsp    = (const int*)d_in[7];

    float* out   = (float*)d_out;
    float* k_out = out;
    float* v_out = out + (size_t)S * NH * H;
    float* attn  = out + 2ull * S * NH * H;

    k_qkv_partial<<<dim3(96, 16), 128>>>(x, w_qkv);
    k_qkv_rope<<<96, 128>>>(segp, tsp, k_out, v_out);
    k_flash<<<dim3(64, NH), 256>>>(k_in, v_in, mask, tsp, k_out, v_out);
    k_combine<<<NH, 512>>>();
    k_out_gemv<<<dim3(8, 64), 128>>>(w_out);
    k_out_reduce<<<8, 128>>>(attn);
}

// round 9
// speedup vs baseline: 1.1071x; 1.0195x over previous
#include <cuda_runtime.h>
#include <cstdint>
#include <cstddef>

#define D    4096
#define NH   32
#define H    128
#define S    4096
#define KMASK (-2.3819763e+38f)

// ---------------- scratch (device globals; no allocation allowed) ----------
__device__ __align__(16) float g_qkvp[16 * 96 * 128];   // qkv gemv partials
__device__ __align__(16) float g_q[NH * H];             // rope'd + scaled q
__device__ __align__(16) float g_knew[NH * H];          // rope'd new k row
__device__ __align__(16) float g_vnew[NH * H];          // new v row
__device__ float g_pm[NH * 64];                         // per-chunk max
__device__ float g_pl[NH * 64];                         // per-chunk sum
__device__ __align__(16) float g_pacc[NH * 64 * H];     // [n][c][h] p·v partials
__device__ __align__(16) float g_enc8[8 * NH * H];      // [cg][nh] combine subpartials
__device__ __align__(16) float g_opart[64 * D];         // [nh-chunk][d]

// ---------------- K1: qkv = x @ w_qkv, partial over D ----------------------
// grid (96, 16): blockIdx.x = s*32+n, blockIdx.y = D-chunk of 256
// block 128: 4 warps each own a 64-d slice; intra-block reduce -> 1 partial
__global__ void __launch_bounds__(128) k_qkv_partial(const float* __restrict__ x,
                                                     const float* __restrict__ w) {
    int sn = blockIdx.x;
    int dchunk = blockIdx.y;
    int tid = threadIdx.x;
    int hv = tid & 31;
    int ds = tid >> 5;

    __shared__ float xs[256];
    int dbase = dchunk * 256;
    for (int i = tid; i < 256; i += 128) xs[i] = x[dbase + i];
    __syncthreads();

    const float4* wv = (const float4*)(w + (size_t)sn * D * H + (size_t)dbase * H);
    float4 acc = make_float4(0.f, 0.f, 0.f, 0.f);
    int d0 = ds * 64;
#pragma unroll 8
    for (int d = d0; d < d0 + 64; ++d) {
        float xv = xs[d];
        float4 wq = wv[d * 32 + hv];
        acc.x += xv * wq.x; acc.y += xv * wq.y;
        acc.z += xv * wq.z; acc.w += xv * wq.w;
    }

    __shared__ float4 racc[4][32];
    racc[ds][hv] = acc;
    __syncthreads();
    if (tid < 32) {
        float4 t = racc[0][hv];
#pragma unroll
        for (int wdx = 1; wdx < 4; ++wdx) {
            float4 o = racc[wdx][hv];
            t.x += o.x; t.y += o.y; t.z += o.z; t.w += o.w;
        }
        ((float4*)g_qkvp)[((size_t)dchunk * 96 + sn) * 32 + hv] = t;
    }
}

// ---------------- K2: reduce partials, RoPE, scatter new rows --------------
__global__ void __launch_bounds__(128) k_qkv_rope(const int* __restrict__ segp,
                                                  const int* __restrict__ tsp,
                                                  float* __restrict__ k_out,
                                                  float* __restrict__ v_out) {
    int sn = blockIdx.x;
    int h = threadIdx.x;
    int s = sn >> 5, n = sn & 31;

    float val = 0.f;
#pragma unroll
    for (int p = 0; p < 16; ++p) val += g_qkvp[((size_t)p * 96 + sn) * 128 + h];

    __shared__ float sm[128];
    sm[h] = val;
    __syncthreads();

    int ts = tsp[0];
    if (s == 2) {
        g_vnew[n * 128 + h] = val;
        v_out[((size_t)ts * NH + n) * H + h] = val;
        return;
    }
    float pos = (float)segp[0];
    int i = h & 63;
    float timescale = powf(10000.f, (float)i * (1.f / 64.f));
    float ang = pos / timescale;
    float sn_, cs;
    sincosf(ang, &sn_, &cs);
    float out;
    if (h < 64) out = sm[h] * cs - sm[h + 64] * sn_;
    else        out = sm[h] * cs + sm[h - 64] * sn_;
    if (s == 0) {
        g_q[n * 128 + h] = out * 0.08838834764831845f;  // head_dim^-0.5
    } else {
        g_knew[n * 128 + h] = out;
        k_out[((size_t)ts * NH + n) * H + h] = out;
    }
}

// ---------------- K3: flash attention + k/v cache copy ---------------------
// grid (64 s-chunks of 64, NH), block 256 = 8 warps; warp does 8 s-rows.
__global__ void __launch_bounds__(256) k_flash(const float* __restrict__ k_in,
                                               const float* __restrict__ v_in,
                                               const float* __restrict__ mask,
                                               const int* __restrict__ tsp,
                                               float* __restrict__ k_out,
                                               float* __restrict__ v_out) {
    int warp = threadIdx.x >> 5;
    int lane = threadIdx.x & 31;
    int n = blockIdx.y;
    int c = blockIdx.x;
    int s0 = c * 64 + warp * 8;
    int ts = tsp[0];

    float4 qq = ((const float4*)g_q)[n * 32 + lane];

    // ---- K rows: front-batched load (MLP 8), copy, dot ----
    float4 kk[8];
#pragma unroll
    for (int i = 0; i < 8; ++i) {
        int s = s0 + i;
        size_t ridx = (((size_t)s * NH + n) * H) >> 2;
        kk[i] = (s == ts) ? ((const float4*)g_knew)[n * 32 + lane]
                          : ((const float4*)k_in)[ridx + lane];
    }
#pragma unroll
    for (int i = 0; i < 8; ++i) {
        int s = s0 + i;
        if (s != ts) {
            size_t ridx = (((size_t)s * NH + n) * H) >> 2;
            ((float4*)k_out)[ridx + lane] = kk[i];
        }
    }

    float lg[8];
#pragma unroll
    for (int i = 0; i < 8; ++i) {
        int s = s0 + i;
        float dot = kk[i].x * qq.x + kk[i].y * qq.y + kk[i].z * qq.z + kk[i].w * qq.w;
#pragma unroll
        for (int off = 16; off; off >>= 1)
            dot += __shfl_xor_sync(0xffffffffu, dot, off);
        lg[i] = (mask[s] >= 0.5f * KMASK) ? dot : KMASK;
    }

    // warp-local softmax over 8 rows
    float m = lg[0];
#pragma unroll
    for (int i = 1; i < 8; ++i) m = fmaxf(m, lg[i]);
    float p[8], l = 0.f;
#pragma unroll
    for (int i = 0; i < 8; ++i) { p[i] = __expf(lg[i] - m); l += p[i]; }

    // ---- V rows: front-batched load, copy, weighted accumulate ----
    float4 vv[8];
#pragma unroll
    for (int i = 0; i < 8; ++i) {
        int s = s0 + i;
        size_t ridx = (((size_t)s * NH + n) * H) >> 2;
        vv[i] = (s == ts) ? ((const float4*)g_vnew)[n * 32 + lane]
                          : ((const float4*)v_in)[ridx + lane];
    }
#pragma unroll
    for (int i = 0; i < 8; ++i) {
        int s = s0 + i;
        if (s != ts) {
            size_t ridx = (((size_t)s * NH + n) * H) >> 2;
            ((float4*)v_out)[ridx + lane] = vv[i];
        }
    }

    float4 acc = make_float4(0.f, 0.f, 0.f, 0.f);
#pragma unroll
    for (int i = 0; i < 8; ++i) {
        acc.x += p[i] * vv[i].x; acc.y += p[i] * vv[i].y;
        acc.z += p[i] * vv[i].z; acc.w += p[i] * vv[i].w;
    }

    // ---- block merge across 8 warps ----
    __shared__ float4 red[8][32];
    __shared__ float sm_m[8], sm_l[8];
    red[warp][lane] = acc;
    if (lane == 0) { sm_m[warp] = m; sm_l[warp] = l; }
    __syncthreads();
    if (warp == 0) {
        float bm = sm_m[0];
#pragma unroll
        for (int w = 1; w < 8; ++w) bm = fmaxf(bm, sm_m[w]);
        float bl = 0.f;
        float4 t = make_float4(0.f, 0.f, 0.f, 0.f);
#pragma unroll
        for (int w = 0; w < 8; ++w) {
            float e = __expf(sm_m[w] - bm);
            bl += sm_l[w] * e;
            float4 o = red[w][lane];
            t.x += e * o.x; t.y += e * o.y; t.z += e * o.z; t.w += e * o.w;
        }
        ((float4*)g_pacc)[((size_t)n * 64 + c) * 32 + lane] = t;   // [n][c][h]
        if (lane == 0) {
            g_pm[n * 64 + c] = bm;
            g_pl[n * 64 + c] = bl;
        }
    }
}

// ---------------- K4: combine chunk partials (parallel, 256 blocks) --------
// grid (8 chunk-groups, NH), block 128 (h); each block sums 8 of 64 chunks
__global__ void __launch_bounds__(128) k_combine() {
    int cg = blockIdx.x;                          // 0..7
    int n = blockIdx.y;
    int tid = threadIdx.x;

    __shared__ float s_m[64], s_l[64], s_e[64];
    __shared__ float s_mg, s_linv;
    if (tid < 64) {
        s_m[tid] = g_pm[n * 64 + tid];
        s_l[tid] = g_pl[n * 64 + tid];
    }
    __syncthreads();
    if (tid < 32) {
        float m = fmaxf(s_m[tid], s_m[tid + 32]);
#pragma unroll
        for (int off = 16; off; off >>= 1)
            m = fmaxf(m, __shfl_xor_sync(0xffffffffu, m, off));
        if (tid == 0) s_mg = m;
    }
    __syncthreads();
    if (tid < 64) s_e[tid] = __expf(s_m[tid] - s_mg);
    __syncthreads();
    if (tid < 32) {
        float l = s_l[tid] * s_e[tid] + s_l[tid + 32] * s_e[tid + 32];
#pragma unroll
        for (int off = 16; off; off >>= 1)
            l += __shfl_xor_sync(0xffffffffu, l, off);
        if (tid == 0) s_linv = 1.f / l;
    }
    __syncthreads();

    const float* base = g_pacc + (size_t)n * 64 * 128;
    float acc = 0.f;
    int c0 = cg * 8;
#pragma unroll
    for (int c = c0; c < c0 + 8; ++c)
        acc += base[c * 128 + tid] * s_e[c];
    g_enc8[((size_t)cg * NH + n) * 128 + tid] = acc * s_linv;
}

// ---------------- K5: output GEMV partials ---------------------------------
// grid (8 d-tiles of 512, 64 nh-chunks of 64), block 128: thread owns 4 d
__global__ void __launch_bounds__(128) k_out_gemv(const float* __restrict__ w_out) {
    __shared__ float enc_s[64];
    int tid = threadIdx.x;
    int nh0 = blockIdx.y * 64;
    if (tid < 64) {
        float v = 0.f;
#pragma unroll
        for (int cg = 0; cg < 8; ++cg)
            v += g_enc8[(size_t)cg * NH * H + nh0 + tid];
        enc_s[tid] = v;
    }
    __syncthreads();

    int d4 = blockIdx.x * 128 + tid;             // float4 index over d
    const float4* wv = (const float4*)w_out;
    float4 acc = make_float4(0.f, 0.f, 0.f, 0.f);
#pragma unroll 8
    for (int j = 0; j < 64; ++j) {
        float e = enc_s[j];
        float4 w4 = wv[(size_t)(nh0 + j) * (D / 4) + d4];
        acc.x += e * w4.x; acc.y += e * w4.y;
        acc.z += e * w4.z; acc.w += e * w4.w;
    }
    ((float4*)g_opart)[(size_t)blockIdx.y * (D / 4) + d4] = acc;
}

// ---------------- K6: final output reduce (float4) -------------------------
__global__ void __launch_bounds__(128) k_out_reduce(float* __restrict__ attn) {
    int d4 = blockIdx.x * 128 + threadIdx.x;     // float4 index over d
    float4 v = make_float4(0.f, 0.f, 0.f, 0.f);
#pragma unroll
    for (int c = 0; c < 64; ++c) {
        float4 o = ((const float4*)g_opart)[(size_t)c * (D / 4) + d4];
        v.x += o.x; v.y += o.y; v.z += o.z; v.w += o.w;
    }
    ((float4*)attn)[d4] = v;
}

// ---------------- launch ----------------------------------------------------
extern "C" void kernel_launch(void* const* d_in, const int* in_sizes, int n_in,
                              void* d_out, int out_size) {
    const float* x      = (const float*)d_in[0];
    const float* w_qkv  = (const float*)d_in[1];
    const float* w_out  = (const float*)d_in[2];
    const float* k_in   = (const float*)d_in[3];
    const float* v_in   = (const float*)d_in[4];
    const float* mask   = (const float*)d_in[5];
    const int*   segp   = (const int*)d_in[6];
    const int*   tsp    = (const int*)d_in[7];

    float* out   = (float*)d_out;
    float* k_out = out;
    float* v_out = out + (size_t)S * NH * H;
    float* attn  = out + 2ull * S * NH * H;

    k_qkv_partial<<<dim3(96, 16), 128>>>(x, w_qkv);
    k_qkv_rope<<<96, 128>>>(segp, tsp, k_out, v_out);
    k_flash<<<dim3(64, NH), 256>>>(k_in, v_in, mask, tsp, k_out, v_out);
    k_combine<<<dim3(8, NH), 128>>>();
    k_out_gemv<<<dim3(8, 64), 128>>>(w_out);
    k_out_reduce<<<8, 128>>>(attn);
}